// round 4
// baseline (speedup 1.0000x reference)
#include <cuda_runtime.h>
#include <cuda_bf16.h>
#include <cstdint>

#define NUM_TAGS 48
#define SEQ_LEN  512
#define BATCH    1024
#define CHUNK    8
#define NCHUNK   (SEQ_LEN / CHUNK)   // 64
#define BPW      2                   // batches per warp
#define NCTA     (BATCH / BPW)       // 512

__device__ float    g_nll[BATCH];
__device__ unsigned g_count = 0;

// ---- packed f32x2 helpers (Blackwell FFMA2 path, PTX-only) ------------------
__device__ __forceinline__ void fma2(uint64_t& d, uint64_t a, uint64_t b) {
    asm("fma.rn.f32x2 %0, %1, %2, %0;" : "+l"(d) : "l"(a), "l"(b));
}
__device__ __forceinline__ uint64_t add2(uint64_t a, uint64_t b) {
    uint64_t d;
    asm("add.rn.f32x2 %0, %1, %2;" : "=l"(d) : "l"(a), "l"(b));
    return d;
}
__device__ __forceinline__ uint64_t pack2(float lo, float hi) {
    uint64_t d;
    asm("mov.b64 %0, {%1, %2};" : "=l"(d) : "f"(lo), "f"(hi));
    return d;
}
__device__ __forceinline__ float lo2(uint64_t v) { return __uint_as_float((uint32_t)v); }
__device__ __forceinline__ float hi2(uint64_t v) { return __uint_as_float((uint32_t)(v >> 32)); }

__device__ __forceinline__ void cp16(uint32_t saddr, const void* g) {
    asm volatile("cp.async.cg.shared.global [%0], [%1], 16;" :: "r"(saddr), "l"(g));
}

// One warp (one CTA) per TWO batch elements: two independent recurrence chains
// per warp for latency hiding. Fused mean-reduce in the last CTA.
__global__ __launch_bounds__(32)
void crf_fused_kernel(const float* __restrict__ emissions,
                      const float* __restrict__ transitions,
                      const int*   __restrict__ tags,
                      const int*   __restrict__ mask,
                      float*       __restrict__ out)
{
    const int lane = threadIdx.x;
    const int h    = lane >> 4;     // input half: i in [24h, 24h+24)
    const int q    = lane & 15;     // output triple: j in {3q, 3q+1, 3q+2}
    const int j0   = 3 * q;
    const int i0   = 24 * h;

    __shared__ __align__(16) float swbuf[2][BPW][NUM_TAGS];        // alpha ping-pong
    __shared__ __align__(16) float sem[2][BPW][CHUNK * NUM_TAGS];  // emission chunks
    __shared__ int smask[BPW][SEQ_LEN];
    __shared__ int stags[BPW][SEQ_LEN];

    const float* em_b[BPW];
    #pragma unroll
    for (int bi = 0; bi < BPW; bi++) {
        int b = BPW * blockIdx.x + bi;
        em_b[bi] = emissions + (size_t)b * SEQ_LEN * NUM_TAGS;
    }

    // --- stage emission chunk 0 (both batches) --------------------------------
    #pragma unroll
    for (int bi = 0; bi < BPW; bi++) {
        uint32_t dst = (uint32_t)__cvta_generic_to_shared(&sem[0][bi][0]);
        #pragma unroll
        for (int r = 0; r < 3; r++)
            cp16(dst + lane * 16 + r * 512, em_b[bi] + lane * 4 + r * 128);
    }
    asm volatile("cp.async.commit_group;");

    // --- tags / mask to shared (vectorized) ------------------------------------
    #pragma unroll
    for (int bi = 0; bi < BPW; bi++) {
        int b = BPW * blockIdx.x + bi;
        const int4* tg = (const int4*)(tags + b * SEQ_LEN);
        const int4* mk = (const int4*)(mask + b * SEQ_LEN);
        #pragma unroll
        for (int r = 0; r < 4; r++) {
            ((int4*)stags[bi])[lane + 32 * r] = tg[lane + 32 * r];
            ((int4*)smask[bi])[lane + 32 * r] = mk[lane + 32 * r];
        }
    }

    // --- E = exp(T): half-column slices, 3 output cols per lane (shared by both
    //     batches — same transition matrix) --------------------------------------
    uint64_t Ec[36];
    #pragma unroll
    for (int c = 0; c < 3; c++)
        #pragma unroll
        for (int k = 0; k < 12; k++)
            Ec[c * 12 + k] = pack2(__expf(transitions[(i0 + 2 * k    ) * NUM_TAGS + j0 + c]),
                                   __expf(transitions[(i0 + 2 * k + 1) * NUM_TAGS + j0 + c]));

    // --- init alphas (linear domain): only tag 0 live ----------------------------
    float w[BPW][3];
    #pragma unroll
    for (int bi = 0; bi < BPW; bi++) {
        w[bi][0] = (q == 0) ? 1.0f : 0.0f;
        w[bi][1] = 0.0f;
        w[bi][2] = 0.0f;
        if (h == 0) {
            swbuf[0][bi][j0]     = w[bi][0];
            swbuf[0][bi][j0 + 1] = w[bi][1];
            swbuf[0][bi][j0 + 2] = w[bi][2];
        }
    }
    __syncwarp();

    // --- gold-path scores (overlaps staged chunk-0 latency) ----------------------
    float sc[BPW];
    #pragma unroll
    for (int bi = 0; bi < BPW; bi++) {
        float s = 0.0f;
        #pragma unroll 4
        for (int t = 1 + lane; t < SEQ_LEN; t += 32) {
            int tc = stags[bi][t], tp = stags[bi][t - 1];
            if (smask[bi][t])
                s += em_b[bi][(size_t)t * NUM_TAGS + tc] + transitions[tp * NUM_TAGS + tc];
        }
        #pragma unroll
        for (int off = 16; off; off >>= 1)
            s += __shfl_xor_sync(0xffffffffu, s, off);
        sc[bi] = s;
    }

    // --- forward recursion: 64 chunks x 8 steps, two chains per warp --------------
    float C[BPW] = {0.0f, 0.0f};
    for (int c = 0; c < NCHUNK; c++) {
        if (c + 1 < NCHUNK) {
            #pragma unroll
            for (int bi = 0; bi < BPW; bi++) {
                uint32_t dst = (uint32_t)__cvta_generic_to_shared(&sem[(c + 1) & 1][bi][0]);
                const float* src = em_b[bi] + (size_t)(c + 1) * CHUNK * NUM_TAGS;
                #pragma unroll
                for (int r = 0; r < 3; r++)
                    cp16(dst + lane * 16 + r * 512, src + lane * 4 + r * 128);
            }
        }
        asm volatile("cp.async.commit_group;");
        asm volatile("cp.async.wait_group 1;");
        __syncwarp();

        #pragma unroll
        for (int u = 0; u < CHUNK; u++) {
            #pragma unroll
            for (int bi = 0; bi < BPW; bi++) {
                const float* eb = sem[c & 1][bi] + u * NUM_TAGS;
                const ulonglong2* wv = (const ulonglong2*)(&swbuf[u & 1][bi][i0]);

                float eE0 = __expf(eb[j0]);
                float eE1 = __expf(eb[j0 + 1]);
                float eE2 = __expf(eb[j0 + 2]);

                uint64_t a0[3] = {0, 0, 0}, a1[3] = {0, 0, 0};
                #pragma unroll
                for (int r = 0; r < 6; r++) {
                    ulonglong2 W = wv[r];
                    #pragma unroll
                    for (int cc = 0; cc < 3; cc++) {
                        fma2(a0[cc], W.x, Ec[cc * 12 + 2 * r]);
                        fma2(a1[cc], W.y, Ec[cc * 12 + 2 * r + 1]);
                    }
                }
                int m = smask[bi][c * CHUNK + u];
                float nv[3];
                #pragma unroll
                for (int cc = 0; cc < 3; cc++) {
                    uint64_t s = add2(a0[cc], a1[cc]);
                    float d = lo2(s) + hi2(s);                  // half-dot
                    d += __shfl_xor_sync(0xffffffffu, d, 16);   // combine halves
                    nv[cc] = d;
                }
                nv[0] *= eE0; nv[1] *= eE1; nv[2] *= eE2;
                w[bi][0] = m ? nv[0] : w[bi][0];
                w[bi][1] = m ? nv[1] : w[bi][1];
                w[bi][2] = m ? nv[2] : w[bi][2];
                if (h == 0) {
                    float* wd = swbuf[(u & 1) ^ 1][bi];
                    wd[j0]     = w[bi][0];
                    wd[j0 + 1] = w[bi][1];
                    wd[j0 + 2] = w[bi][2];
                }
            }
            __syncwarp();
        }

        // renormalize both chains (also at final chunk => logZ == C exactly)
        #pragma unroll
        for (int bi = 0; bi < BPW; bi++) {
            float v = (h == 0) ? (w[bi][0] + w[bi][1] + w[bi][2]) : 0.0f;
            #pragma unroll
            for (int off = 16; off; off >>= 1)
                v += __shfl_xor_sync(0xffffffffu, v, off);
            C[bi] += __logf(v);
            float inv = 1.0f / v;
            w[bi][0] *= inv; w[bi][1] *= inv; w[bi][2] *= inv;
            if (h == 0) {
                swbuf[0][bi][j0]     = w[bi][0];
                swbuf[0][bi][j0 + 1] = w[bi][1];
                swbuf[0][bi][j0 + 2] = w[bi][2];
            }
        }
        __syncwarp();
    }

    if (lane == 0) {
        #pragma unroll
        for (int bi = 0; bi < BPW; bi++) {
            int b = BPW * blockIdx.x + bi;
            float score = sc[bi] + em_b[bi][stags[bi][0]];  // emit[0] always counted
            g_nll[b] = C[bi] - score;                        // logZ == C after final renorm
        }
    }

    // --- fused mean-reduce: last CTA does the deterministic sum -------------------
    unsigned done = 0;
    if (lane == 0) {
        __threadfence();
        done = atomicAdd(&g_count, 1u);
    }
    done = __shfl_sync(0xffffffffu, done, 0);
    if (done == NCTA - 1) {
        __threadfence();
        float v = 0.0f;
        #pragma unroll
        for (int i = lane; i < BATCH; i += 32)
            v += __ldcg(&g_nll[i]);
        #pragma unroll
        for (int off = 16; off; off >>= 1)
            v += __shfl_xor_sync(0xffffffffu, v, off);
        if (lane == 0) {
            out[0] = v * (1.0f / (float)BATCH);
            g_count = 0;   // reset for next graph replay
        }
    }
}

extern "C" void kernel_launch(void* const* d_in, const int* in_sizes, int n_in,
                              void* d_out, int out_size)
{
    const float* emissions   = (const float*)d_in[0];
    const float* transitions = (const float*)d_in[1];
    const int*   tags        = (const int*)d_in[2];
    const int*   mask        = (const int*)d_in[3];
    float*       out         = (float*)d_out;

    crf_fused_kernel<<<NCTA, 32>>>(emissions, transitions, tags, mask, out);
}

// round 5
// speedup vs baseline: 1.2347x; 1.2347x over previous
#include <cuda_runtime.h>
#include <cuda_bf16.h>
#include <cstdint>

#define NUM_TAGS 48
#define SEQ_LEN  512
#define BATCH    1024
#define CHUNK    8
#define NCHUNK   (SEQ_LEN / CHUNK)   // 64
#define WPB      4                   // warps (=batches) per CTA
#define NCTA     (BATCH / WPB)       // 256

__device__ float    g_nll[BATCH];
__device__ unsigned g_count = 0;

// ---- packed f32x2 helpers (Blackwell FFMA2 path, PTX-only) ------------------
__device__ __forceinline__ void fma2(uint64_t& d, uint64_t a, uint64_t b) {
    asm("fma.rn.f32x2 %0, %1, %2, %0;" : "+l"(d) : "l"(a), "l"(b));
}
__device__ __forceinline__ uint64_t add2(uint64_t a, uint64_t b) {
    uint64_t d;
    asm("add.rn.f32x2 %0, %1, %2;" : "=l"(d) : "l"(a), "l"(b));
    return d;
}
__device__ __forceinline__ uint64_t pack2(float lo, float hi) {
    uint64_t d;
    asm("mov.b64 %0, {%1, %2};" : "=l"(d) : "f"(lo), "f"(hi));
    return d;
}
__device__ __forceinline__ float lo2(uint64_t v) { return __uint_as_float((uint32_t)v); }
__device__ __forceinline__ float hi2(uint64_t v) { return __uint_as_float((uint32_t)(v >> 32)); }

__device__ __forceinline__ void cp16(uint32_t saddr, const void* g) {
    asm volatile("cp.async.cg.shared.global [%0], [%1], 16;" :: "r"(saddr), "l"(g));
}

// 4 warps per CTA, each warp owns one batch element (independent, warp-local sync).
__global__ __launch_bounds__(32 * WPB)
void crf_fused_kernel(const float* __restrict__ emissions,
                      const float* __restrict__ transitions,
                      const int*   __restrict__ tags,
                      const int*   __restrict__ mask,
                      float*       __restrict__ out)
{
    const int lane = threadIdx.x & 31;
    const int wid  = threadIdx.x >> 5;
    const int b    = blockIdx.x * WPB + wid;
    const int h    = lane >> 4;     // input half: i in [24h, 24h+24)
    const int q    = lane & 15;     // output triple: j in {3q, 3q+1, 3q+2}
    const int j0   = 3 * q;
    const int i0   = 24 * h;

    __shared__ __align__(16) float swbuf[WPB][2][NUM_TAGS];        // alpha ping-pong
    __shared__ __align__(16) float sem[WPB][2][CHUNK * NUM_TAGS];  // emission chunks
    __shared__ int smask[WPB][SEQ_LEN];
    __shared__ int stags[WPB][SEQ_LEN];

    const float* em_b   = emissions + (size_t)b * SEQ_LEN * NUM_TAGS;
    const int*   tags_b = tags + b * SEQ_LEN;
    const int*   mask_b = mask + b * SEQ_LEN;

    // --- stage emission chunk 0 ------------------------------------------------
    {
        uint32_t dst = (uint32_t)__cvta_generic_to_shared(&sem[wid][0][0]);
        #pragma unroll
        for (int r = 0; r < 3; r++)
            cp16(dst + lane * 16 + r * 512, em_b + lane * 4 + r * 128);
        asm volatile("cp.async.commit_group;");
    }

    // --- tags / mask to shared (vectorized) -------------------------------------
    #pragma unroll
    for (int r = 0; r < 4; r++) {
        ((int4*)stags[wid])[lane + 32 * r] = ((const int4*)tags_b)[lane + 32 * r];
        ((int4*)smask[wid])[lane + 32 * r] = ((const int4*)mask_b)[lane + 32 * r];
    }

    // --- E = exp(T): half-column slices, 3 output cols per lane ------------------
    uint64_t Ec[36];
    #pragma unroll
    for (int c = 0; c < 3; c++)
        #pragma unroll
        for (int k = 0; k < 12; k++)
            Ec[c * 12 + k] = pack2(__expf(transitions[(i0 + 2 * k    ) * NUM_TAGS + j0 + c]),
                                   __expf(transitions[(i0 + 2 * k + 1) * NUM_TAGS + j0 + c]));

    // --- init alphas (linear domain): only tag 0 live -----------------------------
    float w0 = (q == 0) ? 1.0f : 0.0f;
    float w1 = 0.0f, w2 = 0.0f;
    if (h == 0) {
        swbuf[wid][0][j0]     = w0;
        swbuf[wid][0][j0 + 1] = w1;
        swbuf[wid][0][j0 + 2] = w2;
    }
    __syncwarp();

    // --- gold-path score (overlaps staged chunk-0 latency) ------------------------
    float sc = 0.0f;
    #pragma unroll 4
    for (int t = 1 + lane; t < SEQ_LEN; t += 32) {
        int tc = stags[wid][t], tp = stags[wid][t - 1];
        if (smask[wid][t])
            sc += em_b[(size_t)t * NUM_TAGS + tc] + transitions[tp * NUM_TAGS + tc];
    }
    #pragma unroll
    for (int off = 16; off; off >>= 1)
        sc += __shfl_xor_sync(0xffffffffu, sc, off);

    // --- forward recursion: 64 chunks x 8 steps ------------------------------------
    float C = 0.0f;
    for (int c = 0; c < NCHUNK; c++) {
        if (c + 1 < NCHUNK) {
            uint32_t dst = (uint32_t)__cvta_generic_to_shared(&sem[wid][(c + 1) & 1][0]);
            const float* src = em_b + (size_t)(c + 1) * CHUNK * NUM_TAGS;
            #pragma unroll
            for (int r = 0; r < 3; r++)
                cp16(dst + lane * 16 + r * 512, src + lane * 4 + r * 128);
        }
        asm volatile("cp.async.commit_group;");
        asm volatile("cp.async.wait_group 1;");
        __syncwarp();

        const float* eb = sem[wid][c & 1];
        const int*   mb = smask[wid] + c * CHUNK;

        // hoist all emission exps for this chunk off the recurrence chain
        float eE[CHUNK][3];
        #pragma unroll
        for (int u = 0; u < CHUNK; u++) {
            eE[u][0] = __expf(eb[u * NUM_TAGS + j0]);
            eE[u][1] = __expf(eb[u * NUM_TAGS + j0 + 1]);
            eE[u][2] = __expf(eb[u * NUM_TAGS + j0 + 2]);
        }

        #pragma unroll
        for (int u = 0; u < CHUNK; u++) {
            const ulonglong2* wv = (const ulonglong2*)(&swbuf[wid][u & 1][i0]);
            uint64_t a0[3] = {0, 0, 0}, a1[3] = {0, 0, 0};
            #pragma unroll
            for (int r = 0; r < 6; r++) {
                ulonglong2 W = wv[r];
                #pragma unroll
                for (int cc = 0; cc < 3; cc++) {
                    fma2(a0[cc], W.x, Ec[cc * 12 + 2 * r]);
                    fma2(a1[cc], W.y, Ec[cc * 12 + 2 * r + 1]);
                }
            }
            int m = mb[u];
            float nv[3];
            #pragma unroll
            for (int cc = 0; cc < 3; cc++) {
                uint64_t s = add2(a0[cc], a1[cc]);
                float d = lo2(s) + hi2(s);                  // half-dot
                d += __shfl_xor_sync(0xffffffffu, d, 16);   // combine halves
                nv[cc] = d * eE[u][cc];
            }
            w0 = m ? nv[0] : w0;
            w1 = m ? nv[1] : w1;
            w2 = m ? nv[2] : w2;
            if (h == 0) {
                float* wd = swbuf[wid][(u & 1) ^ 1];
                wd[j0]     = w0;
                wd[j0 + 1] = w1;
                wd[j0 + 2] = w2;
            }
            __syncwarp();
        }

        // renormalize (also at the final chunk => logZ == C exactly)
        float v = (h == 0) ? (w0 + w1 + w2) : 0.0f;
        #pragma unroll
        for (int off = 16; off; off >>= 1)
            v += __shfl_xor_sync(0xffffffffu, v, off);
        C += __logf(v);
        float inv = 1.0f / v;
        w0 *= inv; w1 *= inv; w2 *= inv;
        if (h == 0) {
            swbuf[wid][0][j0]     = w0;
            swbuf[wid][0][j0 + 1] = w1;
            swbuf[wid][0][j0 + 2] = w2;
        }
        __syncwarp();
    }

    if (lane == 0) {
        float score = sc + em_b[stags[wid][0]];   // emit[0] always counted
        g_nll[b] = C - score;                      // logZ == C after final renorm
    }

    // --- fused mean-reduce: last CTA does the deterministic sum ---------------------
    __syncthreads();
    __shared__ unsigned sdone;
    if (threadIdx.x == 0) {
        __threadfence();
        sdone = atomicAdd(&g_count, 1u);
    }
    __syncthreads();
    if (sdone == NCTA - 1 && wid == 0) {
        __threadfence();
        float v = 0.0f;
        #pragma unroll
        for (int i = lane; i < BATCH; i += 32)
            v += __ldcg(&g_nll[i]);
        #pragma unroll
        for (int off = 16; off; off >>= 1)
            v += __shfl_xor_sync(0xffffffffu, v, off);
        if (lane == 0) {
            out[0] = v * (1.0f / (float)BATCH);
            g_count = 0;   // reset for next graph replay
        }
    }
}

extern "C" void kernel_launch(void* const* d_in, const int* in_sizes, int n_in,
                              void* d_out, int out_size)
{
    const float* emissions   = (const float*)d_in[0];
    const float* transitions = (const float*)d_in[1];
    const int*   tags        = (const int*)d_in[2];
    const int*   mask        = (const int*)d_in[3];
    float*       out         = (float*)d_out;

    crf_fused_kernel<<<NCTA, 32 * WPB>>>(emissions, transitions, tags, mask, out);
}